// round 9
// baseline (speedup 1.0000x reference)
#include <cuda_runtime.h>

#define NN 100000     // nodes
#define NE 1600000    // edges
#define INF 64        // input features
#define OF 40         // output features
#define NQ (OF / 4)   // 10 float4 quads per row
#define NC 10000      // clusters
#define SNB ((NN + 1023) / 1024)   // 98 scan blocks (tile = 256 thr * 4 items)

// ---- scratch (device globals; no dynamic allocation allowed) ----
__device__ __align__(16) float g_u[NN * OF];
__device__ __align__(16) float g_v[NN * OF];
__device__ __align__(16) int   g_deg[NN];     // in-edge histogram (no self loop)
__device__ __align__(16) float g_dinv[NN];    // rsqrt(deg+1)
__device__ __align__(16) int   g_off[NN];     // CSR row offsets (exclusive scan of deg)
__device__ __align__(16) int   g_cur[NN];     // scatter cursors
__device__ __align__(16) int   g_csr[NE];     // CSR column (source) indices
__device__ __align__(16) int   g_part[SNB];   // per-block totals
__device__ __align__(16) float g_xc[NC * OF];
__device__ __align__(16) int   g_cnt[NC];

__device__ __forceinline__ void red_add_v4(float* p, float4 v) {
    asm volatile("red.global.add.v4.f32 [%0], {%1,%2,%3,%4};"
                 :: "l"(p), "f"(v.x), "f"(v.y), "f"(v.z), "f"(v.w)
                 : "memory");
}

// zero deg/cnt/xc (kernel, not memset: must be IN the captured graph)
__global__ void k_init() {
    int i = blockIdx.x * blockDim.x + threadIdx.x;
    if (i < NN) g_deg[i] = 0;
    if (i < NC) g_cnt[i] = 0;
    if (i < NC * OF) g_xc[i] = 0.f;
}

__global__ void k_hist(const int* __restrict__ row, const int* __restrict__ cl) {
    int i = blockIdx.x * blockDim.x + threadIdx.x;
    if (i < NE) atomicAdd(&g_deg[__ldg(row + i)], 1);
    if (i < NN) atomicAdd(&g_cnt[__ldg(cl + i)], 1);
}

// Pass A: per-block exclusive offsets + block totals + dinv (deg already in regs).
__global__ void __launch_bounds__(256) k_scanA() {
    __shared__ int warp_sums[8];
    int lane = threadIdx.x & 31, wid = threadIdx.x >> 5;
    int idx = blockIdx.x * 1024 + threadIdx.x * 4;

    int4 d = make_int4(0, 0, 0, 0);
    if (idx + 3 < NN) d = *(const int4*)(g_deg + idx);
    else {
        if (idx < NN)     d.x = g_deg[idx];
        if (idx + 1 < NN) d.y = g_deg[idx + 1];
        if (idx + 2 < NN) d.z = g_deg[idx + 2];
    }
    int s3 = d.x + d.y + d.z + d.w;

    int v = s3;
#pragma unroll
    for (int o = 1; o < 32; o <<= 1) {
        int t = __shfl_up_sync(~0u, v, o);
        if (lane >= o) v += t;
    }
    if (lane == 31) warp_sums[wid] = v;
    __syncthreads();
    if (wid == 0) {
        int w = (lane < 8) ? warp_sums[lane] : 0;
#pragma unroll
        for (int o = 1; o < 8; o <<= 1) {
            int t = __shfl_up_sync(~0u, w, o);
            if (lane >= o) w += t;
        }
        if (lane < 8) warp_sums[lane] = w;
    }
    __syncthreads();
    int excl = (v - s3) + (wid ? warp_sums[wid - 1] : 0);

    int e0 = excl, e1 = e0 + d.x, e2 = e1 + d.y, e3 = e2 + d.z;
    if (idx + 3 < NN) {
        *(int4*)(g_off + idx) = make_int4(e0, e1, e2, e3);
        *(float4*)(g_dinv + idx) =
            make_float4(rsqrtf((float)(d.x + 1)), rsqrtf((float)(d.y + 1)),
                        rsqrtf((float)(d.z + 1)), rsqrtf((float)(d.w + 1)));
    } else {
        int ee[4] = {e0, e1, e2, e3};
        int dd[4] = {d.x, d.y, d.z, d.w};
        for (int t = 0; t < 4; t++)
            if (idx + t < NN) {
                g_off[idx + t] = ee[t];
                g_dinv[idx + t] = rsqrtf((float)(dd[t] + 1));
            }
    }
    if (threadIdx.x == 0) g_part[blockIdx.x] = warp_sums[7];
}

// Pass B: each block redundantly computes its base from the 98 partials,
// then finalizes g_off and g_cur.
__global__ void __launch_bounds__(256) k_scanB() {
    __shared__ int sh_part[SNB];
    __shared__ int sh_base;
    for (int t = threadIdx.x; t < SNB; t += blockDim.x) sh_part[t] = g_part[t];
    __syncthreads();
    if (threadIdx.x == 0) {
        int base = 0;
        for (int j = 0; j < (int)blockIdx.x; j++) base += sh_part[j];
        sh_base = base;
    }
    __syncthreads();
    int base = sh_base;
    int idx = blockIdx.x * 1024 + threadIdx.x * 4;
    if (idx + 3 < NN) {
        int4 o = *(const int4*)(g_off + idx);
        o.x += base; o.y += base; o.z += base; o.w += base;
        *(int4*)(g_off + idx) = o;
        *(int4*)(g_cur + idx) = o;
    } else {
        for (int t = 0; t < 4; t++)
            if (idx + t < NN) {
                int o = g_off[idx + t] + base;
                g_off[idx + t] = o;
                g_cur[idx + t] = o;
            }
    }
}

__global__ void k_scatter(const int* __restrict__ row, const int* __restrict__ col) {
    int i = blockIdx.x * blockDim.x + threadIdx.x;
    if (i >= NE) return;
    int r = __ldg(row + i);
    int pos = atomicAdd(&g_cur[r], 1);
    g_csr[pos] = __ldg(col + i);
}

// u0 = dinv * (x @ W^T). TWO threads per node (20 outputs each): 20 scalar
// accumulators -> ~40 regs -> ~2x occupancy vs the 40-acc version. half is
// uniform per warp (tid>>7), so W float4 smem reads are pure broadcasts.
__global__ void __launch_bounds__(256) k_transform(const float* __restrict__ x,
                                                   const float* __restrict__ W) {
    __shared__ float4 Wp[INF * NQ];   // f-major: Wp[f*NQ + oq] = W[4oq..4oq+3][f]
    for (int i = threadIdx.x; i < INF * NQ; i += blockDim.x) {
        int f = i / NQ, oq = i - f * NQ;
        Wp[i] = make_float4(W[(4 * oq + 0) * INF + f], W[(4 * oq + 1) * INF + f],
                            W[(4 * oq + 2) * INF + f], W[(4 * oq + 3) * INF + f]);
    }
    __syncthreads();
    int half = threadIdx.x >> 7;                     // 0 or 1 (warp-uniform)
    int n = blockIdx.x * 128 + (threadIdx.x & 127);
    if (n >= NN) return;

    float acc[20];
#pragma unroll
    for (int k = 0; k < 20; k++) acc[k] = 0.f;

    const float4* xp = (const float4*)(x + (size_t)n * INF);
#pragma unroll 1
    for (int fc = 0; fc < INF; fc += 8) {
        float4 a = __ldg(xp + fc / 4);
        float4 b2 = __ldg(xp + fc / 4 + 1);
        float xs[8] = {a.x, a.y, a.z, a.w, b2.x, b2.y, b2.z, b2.w};
#pragma unroll
        for (int ff = 0; ff < 8; ff++) {
            const float4* wrow = &Wp[(fc + ff) * NQ + half * 5];
#pragma unroll
            for (int k = 0; k < 5; k++) {
                float4 w = wrow[k];
                acc[4 * k + 0] += xs[ff] * w.x;
                acc[4 * k + 1] += xs[ff] * w.y;
                acc[4 * k + 2] += xs[ff] * w.z;
                acc[4 * k + 3] += xs[ff] * w.w;
            }
        }
    }
    float dv = rsqrtf((float)(g_deg[n] + 1));
    float4* up = (float4*)(g_u + (size_t)n * OF + half * 20);
#pragma unroll
    for (int k = 0; k < 5; k++)
        up[k] = make_float4(acc[4 * k] * dv, acc[4 * k + 1] * dv,
                            acc[4 * k + 2] * dv, acc[4 * k + 3] * dv);
}

// Gather hop. DIR=0: g_u -> g_v.  DIR=1: g_v -> g_u.  LAST: g_u -> cluster RED.
// 10 lanes per node (one float4 quad each), 32 nodes per 320-thread block.
template <int DIR, int LAST>
__global__ void __launch_bounds__(320) k_hop(const int* __restrict__ cl) {
    int tid = threadIdx.x;
    int g = tid / NQ;
    int q = tid - g * NQ;
    int n = blockIdx.x * 32 + g;
    if (n >= NN) return;

    const float4* base = (const float4*)(DIR ? g_v : g_u);
    int s = g_off[n];
    int e = s + g_deg[n];
    float4 acc = __ldg(base + (size_t)n * NQ + q);  // self loop

    int j = s;
    for (; j + 4 <= e; j += 4) {
        int c0 = __ldg(g_csr + j);
        int c1 = __ldg(g_csr + j + 1);
        int c2 = __ldg(g_csr + j + 2);
        int c3 = __ldg(g_csr + j + 3);
        float4 a = __ldg(base + (size_t)c0 * NQ + q);
        float4 b2 = __ldg(base + (size_t)c1 * NQ + q);
        float4 c = __ldg(base + (size_t)c2 * NQ + q);
        float4 d = __ldg(base + (size_t)c3 * NQ + q);
        acc.x += a.x + b2.x + c.x + d.x;
        acc.y += a.y + b2.y + c.y + d.y;
        acc.z += a.z + b2.z + c.z + d.z;
        acc.w += a.w + b2.w + c.w + d.w;
    }
    for (; j < e; j++) {
        int c0 = __ldg(g_csr + j);
        float4 a = __ldg(base + (size_t)c0 * NQ + q);
        acc.x += a.x; acc.y += a.y; acc.z += a.z; acc.w += a.w;
    }

    float dv = g_dinv[n];
    float sc = LAST ? dv : dv * dv;
    acc.x *= sc; acc.y *= sc; acc.z *= sc; acc.w *= sc;
    if (LAST) {
        int c = __ldg(cl + n);
        red_add_v4(g_xc + (size_t)c * OF + q * 4, acc);
    } else {
        float4* outp = (float4*)(DIR ? g_u : g_v);
        outp[(size_t)n * NQ + q] = acc;
    }
}

// out[n] = xc[cluster[n]] / max(cnt,1) + b
__global__ void k_out(const int* __restrict__ cl, const float* __restrict__ b,
                      float* __restrict__ out) {
    int i = blockIdx.x * blockDim.x + threadIdx.x;
    if (i >= NN * NQ) return;
    int n = i / NQ;
    int q = i - n * NQ;
    int c = __ldg(cl + n);
    float s = 1.0f / (float)max(g_cnt[c], 1);
    float4 t = ((const float4*)g_xc)[c * NQ + q];
    float4 bb = ((const float4*)b)[q];
    float4 o;
    o.x = t.x * s + bb.x;
    o.y = t.y * s + bb.y;
    o.z = t.z * s + bb.z;
    o.w = t.w * s + bb.w;
    ((float4*)out)[i] = o;
}

// side stream + events: created ONCE on the first (correctness, non-captured)
// call via magic static; work per call is identical, so determinism holds.
struct Aux {
    cudaStream_t s2;
    cudaEvent_t ev0, ev2;
    bool ok;
    Aux() {
        ok = (cudaStreamCreateWithFlags(&s2, cudaStreamNonBlocking) == cudaSuccess) &&
             (cudaEventCreateWithFlags(&ev0, cudaEventDisableTiming) == cudaSuccess) &&
             (cudaEventCreateWithFlags(&ev2, cudaEventDisableTiming) == cudaSuccess);
    }
};

extern "C" void kernel_launch(void* const* d_in, const int* in_sizes, int n_in,
                              void* d_out, int out_size) {
    const float* x = nullptr;
    const int* ei = nullptr;
    const int* cl = nullptr;
    const float* W = nullptr;
    const float* b = nullptr;
    for (int i = 0; i < n_in; i++) {
        switch (in_sizes[i]) {
            case NN * INF: x = (const float*)d_in[i]; break;
            case 2 * NE:   ei = (const int*)d_in[i]; break;
            case NN:       cl = (const int*)d_in[i]; break;
            case OF * INF: W = (const float*)d_in[i]; break;
            case OF:       b = (const float*)d_in[i]; break;
            default: break;
        }
    }
    const int* row = ei;        // targets
    const int* col = ei + NE;   // sources

    static Aux aux;             // first call is the (uncaptured) correctness run

    const int B = 256;
    k_init<<<(NC * OF + B - 1) / B, B>>>();
    k_hist<<<(NE + B - 1) / B, B>>>(row, cl);

    if (aux.ok) {
        // fork: transform on s2, CSR build on legacy — independent paths
        cudaEventRecord(aux.ev0, 0);
        cudaStreamWaitEvent(aux.s2, aux.ev0, 0);
        k_transform<<<(NN + 127) / 128, 256, 0, aux.s2>>>(x, W);
        cudaEventRecord(aux.ev2, aux.s2);

        k_scanA<<<SNB, 256>>>();
        k_scanB<<<SNB, 256>>>();
        k_scatter<<<(NE + B - 1) / B, B>>>(row, col);
        cudaStreamWaitEvent(0, aux.ev2, 0);   // join before hops
    } else {
        k_scanA<<<SNB, 256>>>();
        k_scanB<<<SNB, 256>>>();
        k_scatter<<<(NE + B - 1) / B, B>>>(row, col);
        k_transform<<<(NN + 127) / 128, 256>>>(x, W);
    }

    const int HG = (NN + 31) / 32;
    k_hop<0, 0><<<HG, 320>>>(cl);   // u -> v
    k_hop<1, 0><<<HG, 320>>>(cl);   // v -> u
    k_hop<0, 1><<<HG, 320>>>(cl);   // u -> cluster sums
    k_out<<<(NN * NQ + B - 1) / B, B>>>(cl, b, (float*)d_out);
}

// round 10
// speedup vs baseline: 1.0190x; 1.0190x over previous
#include <cuda_runtime.h>

#define NN 100000     // nodes
#define NE 1600000    // edges
#define INF 64        // input features
#define OF 40         // output features
#define NQ (OF / 4)   // 10 float4 quads per row
#define NC 10000      // clusters
#define SNB ((NN + 1023) / 1024)   // 98 scan blocks (tile = 256 thr * 4 items)

// ---- scratch (device globals; no dynamic allocation allowed) ----
__device__ __align__(16) float g_u[NN * OF];
__device__ __align__(16) float g_v[NN * OF];
__device__ __align__(16) int   g_deg[NN];     // in-edge histogram (no self loop)
__device__ __align__(16) float g_dinv[NN];    // rsqrt(deg+1)
__device__ __align__(16) int   g_off[NN];     // CSR row offsets (exclusive scan of deg)
__device__ __align__(16) int   g_cur[NN];     // scatter cursors
__device__ __align__(16) int   g_csr[NE];     // CSR column (source) indices
__device__ __align__(16) int   g_part[SNB];   // per-block totals
__device__ __align__(16) float g_xc[NC * OF];
__device__ __align__(16) int   g_cnt[NC];

__device__ __forceinline__ void red_add_v4(float* p, float4 v) {
    asm volatile("red.global.add.v4.f32 [%0], {%1,%2,%3,%4};"
                 :: "l"(p), "f"(v.x), "f"(v.y), "f"(v.z), "f"(v.w)
                 : "memory");
}

// zero deg/cnt/xc (kernel, not memset: must be IN the captured graph)
__global__ void k_init() {
    int i = blockIdx.x * blockDim.x + threadIdx.x;
    if (i < NN) g_deg[i] = 0;
    if (i < NC) g_cnt[i] = 0;
    if (i < NC * OF) g_xc[i] = 0.f;
}

__global__ void k_hist(const int* __restrict__ row, const int* __restrict__ cl) {
    int i = blockIdx.x * blockDim.x + threadIdx.x;
    if (i < NE) atomicAdd(&g_deg[__ldg(row + i)], 1);
    if (i < NN) atomicAdd(&g_cnt[__ldg(cl + i)], 1);
}

// Pass A: per-block exclusive offsets + block totals + dinv (deg already in regs).
__global__ void __launch_bounds__(256) k_scanA() {
    __shared__ int warp_sums[8];
    int lane = threadIdx.x & 31, wid = threadIdx.x >> 5;
    int idx = blockIdx.x * 1024 + threadIdx.x * 4;

    int4 d = make_int4(0, 0, 0, 0);
    if (idx + 3 < NN) d = *(const int4*)(g_deg + idx);
    else {
        if (idx < NN)     d.x = g_deg[idx];
        if (idx + 1 < NN) d.y = g_deg[idx + 1];
        if (idx + 2 < NN) d.z = g_deg[idx + 2];
    }
    int s3 = d.x + d.y + d.z + d.w;

    int v = s3;
#pragma unroll
    for (int o = 1; o < 32; o <<= 1) {
        int t = __shfl_up_sync(~0u, v, o);
        if (lane >= o) v += t;
    }
    if (lane == 31) warp_sums[wid] = v;
    __syncthreads();
    if (wid == 0) {
        int w = (lane < 8) ? warp_sums[lane] : 0;
#pragma unroll
        for (int o = 1; o < 8; o <<= 1) {
            int t = __shfl_up_sync(~0u, w, o);
            if (lane >= o) w += t;
        }
        if (lane < 8) warp_sums[lane] = w;
    }
    __syncthreads();
    int excl = (v - s3) + (wid ? warp_sums[wid - 1] : 0);

    int e0 = excl, e1 = e0 + d.x, e2 = e1 + d.y, e3 = e2 + d.z;
    if (idx + 3 < NN) {
        *(int4*)(g_off + idx) = make_int4(e0, e1, e2, e3);
        *(float4*)(g_dinv + idx) =
            make_float4(rsqrtf((float)(d.x + 1)), rsqrtf((float)(d.y + 1)),
                        rsqrtf((float)(d.z + 1)), rsqrtf((float)(d.w + 1)));
    } else {
        int ee[4] = {e0, e1, e2, e3};
        int dd[4] = {d.x, d.y, d.z, d.w};
        for (int t = 0; t < 4; t++)
            if (idx + t < NN) {
                g_off[idx + t] = ee[t];
                g_dinv[idx + t] = rsqrtf((float)(dd[t] + 1));
            }
    }
    if (threadIdx.x == 0) g_part[blockIdx.x] = warp_sums[7];
}

// Pass B: each block redundantly computes its base from the 98 partials,
// then finalizes g_off and g_cur.
__global__ void __launch_bounds__(256) k_scanB() {
    __shared__ int sh_part[SNB];
    __shared__ int sh_base;
    for (int t = threadIdx.x; t < SNB; t += blockDim.x) sh_part[t] = g_part[t];
    __syncthreads();
    if (threadIdx.x == 0) {
        int base = 0;
        for (int j = 0; j < (int)blockIdx.x; j++) base += sh_part[j];
        sh_base = base;
    }
    __syncthreads();
    int base = sh_base;
    int idx = blockIdx.x * 1024 + threadIdx.x * 4;
    if (idx + 3 < NN) {
        int4 o = *(const int4*)(g_off + idx);
        o.x += base; o.y += base; o.z += base; o.w += base;
        *(int4*)(g_off + idx) = o;
        *(int4*)(g_cur + idx) = o;
    } else {
        for (int t = 0; t < 4; t++)
            if (idx + t < NN) {
                int o = g_off[idx + t] + base;
                g_off[idx + t] = o;
                g_cur[idx + t] = o;
            }
    }
}

__global__ void k_scatter(const int* __restrict__ row, const int* __restrict__ col) {
    int i = blockIdx.x * blockDim.x + threadIdx.x;
    if (i >= NE) return;
    int r = __ldg(row + i);
    int pos = atomicAdd(&g_cur[r], 1);
    g_csr[pos] = __ldg(col + i);
}

// u0 = dinv * (x @ W^T). TWO NODES per thread, f32x2 accumulators:
// each W smem read (ulonglong2) feeds FMAs for both nodes -> LDS traffic
// halves vs one-node-per-thread (the measured limiter: L1=69.5% in R8).
// Node mapping: n0 = blk*512 + t, n1 = n0 + 256 (x rows loaded once each).
__global__ void __launch_bounds__(256) k_transform(const float* __restrict__ x,
                                                   const float* __restrict__ W) {
    __shared__ float Wp[INF * OF];   // f-major: Wp[f*OF + o]
    for (int i = threadIdx.x; i < INF * OF; i += blockDim.x) {
        int f = i / OF, o = i - f * OF;
        Wp[i] = W[o * INF + f];
    }
    __syncthreads();
    int n0 = blockIdx.x * 512 + threadIdx.x;
    int n1 = n0 + 256;
    if (n0 >= NN) return;
    bool has1 = (n1 < NN);

    unsigned long long a0[OF / 2], a1[OF / 2];
#pragma unroll
    for (int p = 0; p < OF / 2; p++) { a0[p] = 0ull; a1[p] = 0ull; }

    const float4* xp0 = (const float4*)(x + (size_t)n0 * INF);
    const float4* xp1 = (const float4*)(x + (size_t)n1 * INF);
#pragma unroll 1
    for (int fc = 0; fc < INF; fc += 4) {
        float4 va = __ldg(xp0 + fc / 4);
        float4 vb = has1 ? __ldg(xp1 + fc / 4) : make_float4(0.f, 0.f, 0.f, 0.f);
        float xs0[4] = {va.x, va.y, va.z, va.w};
        float xs1[4] = {vb.x, vb.y, vb.z, vb.w};
#pragma unroll
        for (int ff = 0; ff < 4; ff++) {
            int f = fc + ff;
            unsigned long long x0, x1;
            asm("mov.b64 %0, {%1, %1};" : "=l"(x0) : "f"(xs0[ff]));
            asm("mov.b64 %0, {%1, %1};" : "=l"(x1) : "f"(xs1[ff]));
            const ulonglong2* wrow = (const ulonglong2*)(Wp + f * OF);
#pragma unroll
            for (int p = 0; p < NQ; p++) {
                ulonglong2 w = wrow[p];
                asm("fma.rn.f32x2 %0, %1, %2, %0;" : "+l"(a0[2 * p]) : "l"(w.x), "l"(x0));
                asm("fma.rn.f32x2 %0, %1, %2, %0;" : "+l"(a0[2 * p + 1]) : "l"(w.y), "l"(x0));
                asm("fma.rn.f32x2 %0, %1, %2, %0;" : "+l"(a1[2 * p]) : "l"(w.x), "l"(x1));
                asm("fma.rn.f32x2 %0, %1, %2, %0;" : "+l"(a1[2 * p + 1]) : "l"(w.y), "l"(x1));
            }
        }
    }
    {
        float dv = rsqrtf((float)(g_deg[n0] + 1));
        unsigned long long dd;
        asm("mov.b64 %0, {%1, %1};" : "=l"(dd) : "f"(dv));
        ulonglong2* up = (ulonglong2*)(g_u + (size_t)n0 * OF);
#pragma unroll
        for (int p = 0; p < NQ; p++) {
            unsigned long long r0, r1;
            asm("mul.rn.f32x2 %0, %1, %2;" : "=l"(r0) : "l"(a0[2 * p]), "l"(dd));
            asm("mul.rn.f32x2 %0, %1, %2;" : "=l"(r1) : "l"(a0[2 * p + 1]), "l"(dd));
            ulonglong2 st; st.x = r0; st.y = r1;
            up[p] = st;
        }
    }
    if (has1) {
        float dv = rsqrtf((float)(g_deg[n1] + 1));
        unsigned long long dd;
        asm("mov.b64 %0, {%1, %1};" : "=l"(dd) : "f"(dv));
        ulonglong2* up = (ulonglong2*)(g_u + (size_t)n1 * OF);
#pragma unroll
        for (int p = 0; p < NQ; p++) {
            unsigned long long r0, r1;
            asm("mul.rn.f32x2 %0, %1, %2;" : "=l"(r0) : "l"(a1[2 * p]), "l"(dd));
            asm("mul.rn.f32x2 %0, %1, %2;" : "=l"(r1) : "l"(a1[2 * p + 1]), "l"(dd));
            ulonglong2 st; st.x = r0; st.y = r1;
            up[p] = st;
        }
    }
}

// Gather hop. DIR=0: g_u -> g_v.  DIR=1: g_v -> g_u.  LAST: g_u -> cluster RED.
// 10 lanes per node (one float4 quad each), 32 nodes per 320-thread block.
template <int DIR, int LAST>
__global__ void __launch_bounds__(320) k_hop(const int* __restrict__ cl) {
    int tid = threadIdx.x;
    int g = tid / NQ;
    int q = tid - g * NQ;
    int n = blockIdx.x * 32 + g;
    if (n >= NN) return;

    const float4* base = (const float4*)(DIR ? g_v : g_u);
    int s = g_off[n];
    int e = s + g_deg[n];
    float4 acc = __ldg(base + (size_t)n * NQ + q);  // self loop

    int j = s;
    for (; j + 4 <= e; j += 4) {
        int c0 = __ldg(g_csr + j);
        int c1 = __ldg(g_csr + j + 1);
        int c2 = __ldg(g_csr + j + 2);
        int c3 = __ldg(g_csr + j + 3);
        float4 a = __ldg(base + (size_t)c0 * NQ + q);
        float4 b2 = __ldg(base + (size_t)c1 * NQ + q);
        float4 c = __ldg(base + (size_t)c2 * NQ + q);
        float4 d = __ldg(base + (size_t)c3 * NQ + q);
        acc.x += a.x + b2.x + c.x + d.x;
        acc.y += a.y + b2.y + c.y + d.y;
        acc.z += a.z + b2.z + c.z + d.z;
        acc.w += a.w + b2.w + c.w + d.w;
    }
    for (; j < e; j++) {
        int c0 = __ldg(g_csr + j);
        float4 a = __ldg(base + (size_t)c0 * NQ + q);
        acc.x += a.x; acc.y += a.y; acc.z += a.z; acc.w += a.w;
    }

    float dv = g_dinv[n];
    float sc = LAST ? dv : dv * dv;
    acc.x *= sc; acc.y *= sc; acc.z *= sc; acc.w *= sc;
    if (LAST) {
        int c = __ldg(cl + n);
        red_add_v4(g_xc + (size_t)c * OF + q * 4, acc);
    } else {
        float4* outp = (float4*)(DIR ? g_u : g_v);
        outp[(size_t)n * NQ + q] = acc;
    }
}

// out[n] = xc[cluster[n]] / max(cnt,1) + b
__global__ void k_out(const int* __restrict__ cl, const float* __restrict__ b,
                      float* __restrict__ out) {
    int i = blockIdx.x * blockDim.x + threadIdx.x;
    if (i >= NN * NQ) return;
    int n = i / NQ;
    int q = i - n * NQ;
    int c = __ldg(cl + n);
    float s = 1.0f / (float)max(g_cnt[c], 1);
    float4 t = ((const float4*)g_xc)[c * NQ + q];
    float4 bb = ((const float4*)b)[q];
    float4 o;
    o.x = t.x * s + bb.x;
    o.y = t.y * s + bb.y;
    o.z = t.z * s + bb.z;
    o.w = t.w * s + bb.w;
    ((float4*)out)[i] = o;
}

// side stream + events: created ONCE on the first (correctness, non-captured)
// call via magic static; work per call is identical, so determinism holds.
struct Aux {
    cudaStream_t s2;
    cudaEvent_t ev0, ev2;
    bool ok;
    Aux() {
        ok = (cudaStreamCreateWithFlags(&s2, cudaStreamNonBlocking) == cudaSuccess) &&
             (cudaEventCreateWithFlags(&ev0, cudaEventDisableTiming) == cudaSuccess) &&
             (cudaEventCreateWithFlags(&ev2, cudaEventDisableTiming) == cudaSuccess);
    }
};

extern "C" void kernel_launch(void* const* d_in, const int* in_sizes, int n_in,
                              void* d_out, int out_size) {
    const float* x = nullptr;
    const int* ei = nullptr;
    const int* cl = nullptr;
    const float* W = nullptr;
    const float* b = nullptr;
    for (int i = 0; i < n_in; i++) {
        switch (in_sizes[i]) {
            case NN * INF: x = (const float*)d_in[i]; break;
            case 2 * NE:   ei = (const int*)d_in[i]; break;
            case NN:       cl = (const int*)d_in[i]; break;
            case OF * INF: W = (const float*)d_in[i]; break;
            case OF:       b = (const float*)d_in[i]; break;
            default: break;
        }
    }
    const int* row = ei;        // targets
    const int* col = ei + NE;   // sources

    static Aux aux;             // first call is the (uncaptured) correctness run

    const int B = 256;
    k_init<<<(NC * OF + B - 1) / B, B>>>();
    k_hist<<<(NE + B - 1) / B, B>>>(row, cl);

    const int TG = (NN + 511) / 512;   // 512 nodes per transform block
    if (aux.ok) {
        // fork: transform on s2, CSR build on legacy — independent paths
        cudaEventRecord(aux.ev0, 0);
        cudaStreamWaitEvent(aux.s2, aux.ev0, 0);
        k_transform<<<TG, 256, 0, aux.s2>>>(x, W);
        cudaEventRecord(aux.ev2, aux.s2);

        k_scanA<<<SNB, 256>>>();
        k_scanB<<<SNB, 256>>>();
        k_scatter<<<(NE + B - 1) / B, B>>>(row, col);
        cudaStreamWaitEvent(0, aux.ev2, 0);   // join before hops
    } else {
        k_scanA<<<SNB, 256>>>();
        k_scanB<<<SNB, 256>>>();
        k_scatter<<<(NE + B - 1) / B, B>>>(row, col);
        k_transform<<<TG, 256>>>(x, W);
    }

    const int HG = (NN + 31) / 32;
    k_hop<0, 0><<<HG, 320>>>(cl);   // u -> v
    k_hop<1, 0><<<HG, 320>>>(cl);   // v -> u
    k_hop<0, 1><<<HG, 320>>>(cl);   // u -> cluster sums
    k_out<<<(NN * NQ + B - 1) / B, B>>>(cl, b, (float*)d_out);
}